// round 7
// baseline (speedup 1.0000x reference)
#include <cuda_runtime.h>
#include <cuda_fp16.h>
#include <cstdint>

// out = 0.9*p + 0.1 * softmax(-4 p p^T) p    N=16384, D=64, fp32
// FA2 flash attention: f16 hi QK + e4m3 fp8 cross-term QK, f16 PV.

#define D_DIM 64
#define TM    64
#define TN    64
#define NTH   128
#define PN    (16384*64)
#define QSCALE 5.770780163555854f   // 4*log2(e)
#define S9     512.0f
#define IS9    0.001953125f         // 2^-9

__device__ __half g_qh[PN];                  // fp16(QSCALE*p)
__device__ __half g_ph[PN];                  // fp16(p)  (K hi / V)
__device__ unsigned char g_qx[16384 * 128];  // [e4m3(q) | e4m3(512*ql)] per row
__device__ unsigned char g_kx[16384 * 128];  // [e4m3(512*kl) | e4m3(k)] per row

__device__ __forceinline__ uint32_t smem_u32(const void* p) {
    uint32_t a;
    asm("{ .reg .u64 t; cvta.to.shared.u64 t, %1; cvt.u32.u64 %0, t; }" : "=r"(a) : "l"(p));
    return a;
}
#define SWZ(x) ((x) ^ (((x) >> 3) & 0x70))

#define CP16(dst, src) asm volatile("cp.async.ca.shared.global [%0], [%1], 16;" :: "r"(dst), "l"(src))
#define CP_COMMIT()    asm volatile("cp.async.commit_group;" ::: "memory")
#define CP_WAIT0()     asm volatile("cp.async.wait_group 0;" ::: "memory")

#define LDSM4(r0, r1, r2, r3, a) \
    asm volatile("ldmatrix.sync.aligned.m8n8.x4.shared.b16 {%0,%1,%2,%3}, [%4];" \
        : "=r"(r0), "=r"(r1), "=r"(r2), "=r"(r3) : "r"(a))
#define LDSM4T(r0, r1, r2, r3, a) \
    asm volatile("ldmatrix.sync.aligned.m8n8.x4.trans.shared.b16 {%0,%1,%2,%3}, [%4];" \
        : "=r"(r0), "=r"(r1), "=r"(r2), "=r"(r3) : "r"(a))

__device__ __forceinline__ void mma16816(float* c, const uint32_t a[4], uint32_t b0, uint32_t b1) {
    asm volatile("mma.sync.aligned.m16n8k16.row.col.f32.f16.f16.f32 "
        "{%0,%1,%2,%3},{%4,%5,%6,%7},{%8,%9},{%0,%1,%2,%3};"
        : "+f"(c[0]), "+f"(c[1]), "+f"(c[2]), "+f"(c[3])
        : "r"(a[0]), "r"(a[1]), "r"(a[2]), "r"(a[3]), "r"(b0), "r"(b1));
}
__device__ __forceinline__ void mma16816r(float* c, uint32_t a0, uint32_t a1, uint32_t a2, uint32_t a3,
                                          uint32_t b0, uint32_t b1) {
    asm volatile("mma.sync.aligned.m16n8k16.row.col.f32.f16.f16.f32 "
        "{%0,%1,%2,%3},{%4,%5,%6,%7},{%8,%9},{%0,%1,%2,%3};"
        : "+f"(c[0]), "+f"(c[1]), "+f"(c[2]), "+f"(c[3])
        : "r"(a0), "r"(a1), "r"(a2), "r"(a3), "r"(b0), "r"(b1));
}
__device__ __forceinline__ void mma8(float* c, const uint32_t a[4], uint32_t b0, uint32_t b1) {
    asm volatile("mma.sync.aligned.m16n8k32.row.col.f32.e4m3.e4m3.f32 "
        "{%0,%1,%2,%3},{%4,%5,%6,%7},{%8,%9},{%0,%1,%2,%3};"
        : "+f"(c[0]), "+f"(c[1]), "+f"(c[2]), "+f"(c[3])
        : "r"(a[0]), "r"(a[1]), "r"(a[2]), "r"(a[3]), "r"(b0), "r"(b1));
}
__device__ __forceinline__ float ex2(float x) {
    float r; asm("ex2.approx.ftz.f32 %0, %1;" : "=f"(r) : "f"(x)); return r;
}
__device__ __forceinline__ uint32_t packh(float lo, float hi) {
    uint32_t r; asm("cvt.rn.f16x2.f32 %0, %2, %1;" : "=r"(r) : "f"(lo), "f"(hi)); return r;
}
__device__ __forceinline__ uint32_t ex2h2(uint32_t x) {
    uint32_t r; asm("ex2.approx.f16x2 %0, %1;" : "=r"(r) : "r"(x)); return r;
}
__device__ __forceinline__ uint32_t hadd2u(uint32_t a, uint32_t b) {
    uint32_t r; asm("add.rn.f16x2 %0, %1, %2;" : "=r"(r) : "r"(a), "r"(b)); return r;
}
__device__ __forceinline__ unsigned short pack8(float lo, float hi) {
    unsigned short e;
    asm("cvt.rn.satfinite.e4m3x2.f32 %0, %1, %2;" : "=h"(e) : "f"(hi), "f"(lo));
    return e;
}

__global__ void prep_kernel(const float* __restrict__ p, int n) {
    int i = blockIdx.x * blockDim.x + threadIdx.x;
    int j = 2 * i;
    if (j < n) {
        float x0 = p[j], x1 = p[j + 1];
        __half h0 = __float2half_rn(x0), h1 = __float2half_rn(x1);
        *(__half2*)(g_ph + j) = __halves2half2(h0, h1);
        float l0 = x0 - __half2float(h0), l1 = x1 - __half2float(h1);
        float q0 = QSCALE * x0, q1 = QSCALE * x1;
        __half qh0 = __float2half_rn(q0), qh1 = __float2half_rn(q1);
        *(__half2*)(g_qh + j) = __halves2half2(qh0, qh1);
        float ql0 = q0 - __half2float(qh0), ql1 = q1 - __half2float(qh1);
        int r = j >> 6, d = j & 63;
        *(unsigned short*)(g_kx + r * 128 + d)      = pack8(S9 * l0, S9 * l1);
        *(unsigned short*)(g_kx + r * 128 + 64 + d) = pack8(x0, x1);
        *(unsigned short*)(g_qx + r * 128 + d)      = pack8(q0, q1);
        *(unsigned short*)(g_qx + r * 128 + 64 + d) = pack8(S9 * ql0, S9 * ql1);
    }
}

__global__ void __launch_bounds__(NTH, 2)
attn_kernel(const float* __restrict__ p, float* __restrict__ out, int N) {
    __shared__ __align__(128) char sK[2][16384];   // Kh(8K) + KX fp8(8K), x2 buffers
    __shared__ __align__(128) char sQ[16384];      // Qh(8K) + QX fp8(8K)

    const int tid  = threadIdx.x;
    const int wid  = tid >> 5;
    const int lane = tid & 31;
    const int NT   = N / TN;
    const uint32_t kbase[2] = { smem_u32(sK[0]), smem_u32(sK[1]) };
    const uint32_t qbase    = smem_u32(sQ);

    {   // stage Q (f16 hi + fp8 concat) and K tile 0
        const char* sqh = (const char*)g_qh;
        const char* sph = (const char*)g_ph;
        const size_t qoff = (size_t)blockIdx.x * 8192;
        #pragma unroll
        for (int r = 0; r < 4; r++) {
            int c = tid + r * NTH;
            uint32_t sw = SWZ(c * 16);
            CP16(qbase + sw,           sqh + qoff + c * 16);
            CP16(qbase + 8192 + sw,    (const char*)g_qx + qoff + c * 16);
            CP16(kbase[0] + sw,        sph + c * 16);
            CP16(kbase[0] + 8192 + sw, (const char*)g_kx + c * 16);
        }
        CP_COMMIT();
        CP_WAIT0();
        __syncthreads();
    }

    // Q fragments: f16 hi (A) and fp8 concat (A8), persistent
    uint32_t qh[4][4], a8[4][4];
    {
        const int qrow = wid * 16 + (lane & 7) + ((lane >> 3) & 1) * 8;
        const int qb16 = ((lane >> 4) & 1) * 16;
        #pragma unroll
        for (int kb = 0; kb < 4; kb++) {
            uint32_t off = SWZ((uint32_t)(qrow * 128 + kb * 32 + qb16));
            LDSM4(qh[kb][0], qh[kb][1], qh[kb][2], qh[kb][3], qbase + off);
            LDSM4(a8[kb][0], a8[kb][1], a8[kb][2], a8[kb][3], qbase + 8192 + off);
        }
    }

    float O[32];
    #pragma unroll
    for (int i = 0; i < 32; i++) O[i] = 0.f;
    float m0 = 1e30f, m1 = 1e30f, l0 = 0.f, l1 = 0.f;   // running MIN of T

    const uint32_t koffA = (uint32_t)((lane & 7) * 128 + (lane >> 3) * 16);
    const int vrow  = (lane & 7) + ((lane >> 3) & 1) * 8;
    const uint32_t vb16 = ((lane >> 4) & 1) * 16;

    const char* sph = (const char*)g_ph;

    for (int t = 0; t < NT; t++) {
        const uint32_t kb_ = kbase[t & 1];

        if (t + 1 < NT) {
            const uint32_t nb_ = kbase[(t + 1) & 1];
            const size_t src = (size_t)(t + 1) * 8192;
            #pragma unroll
            for (int r = 0; r < 4; r++) {
                int c = tid + r * NTH;
                uint32_t sw = SWZ(c * 16);
                CP16(nb_ + sw,        sph + src + c * 16);
                CP16(nb_ + 8192 + sw, (const char*)g_kx + src + c * 16);
            }
        }
        CP_COMMIT();

        // ---- fp8 cross pass: S = 2^9 * (qh*kl + ql*kh) ----
        float S[32];
        #pragma unroll
        for (int i = 0; i < 32; i++) S[i] = 0.f;
        #pragma unroll
        for (int nb = 0; nb < 8; nb++) {
            uint32_t base = (uint32_t)(nb * 1024) + koffA;
            uint32_t b0, b1, b2, b3, b4, b5, b6, b7;
            LDSM4(b0, b1, b2, b3, kb_ + 8192 + SWZ(base));       // fp8 k 0..63
            LDSM4(b4, b5, b6, b7, kb_ + 8192 + SWZ(base + 64));  // fp8 k 64..127
            mma8(S + nb * 4, a8[0], b0, b1);
            mma8(S + nb * 4, a8[1], b2, b3);
            mma8(S + nb * 4, a8[2], b4, b5);
            mma8(S + nb * 4, a8[3], b6, b7);
        }
        #pragma unroll
        for (int i = 0; i < 32; i++) S[i] *= IS9;

        // ---- f16 hi pass: S += Qh*Kh ----
        #pragma unroll
        for (int c = 0; c < 2; c++) {
            #pragma unroll
            for (int nb = 0; nb < 8; nb++) {
                uint32_t off = SWZ((uint32_t)(nb * 1024 + c * 64) + koffA);
                uint32_t f0, f1, f2, f3;
                LDSM4(f0, f1, f2, f3, kb_ + off);
                mma16816(S + nb * 4, qh[2 * c],     f0, f1);
                mma16816(S + nb * 4, qh[2 * c + 1], f2, f3);
            }
        }

        // ---- online softmax (logit = -T, track min of T), balanced trees ----
        float mc0, mc1;
        {
            float t0[4], t1[4];
            #pragma unroll
            for (int k = 0; k < 4; k++) {
                t0[k] = fminf(fminf(S[k * 8 + 0], S[k * 8 + 1]), fminf(S[k * 8 + 4], S[k * 8 + 5]));
                t1[k] = fminf(fminf(S[k * 8 + 2], S[k * 8 + 3]), fminf(S[k * 8 + 6], S[k * 8 + 7]));
            }
            mc0 = fminf(fminf(t0[0], t0[1]), fminf(t0[2], t0[3]));
            mc1 = fminf(fminf(t1[0], t1[1]), fminf(t1[2], t1[3]));
        }
        mc0 = fminf(mc0, __shfl_xor_sync(0xffffffffu, mc0, 1));
        mc0 = fminf(mc0, __shfl_xor_sync(0xffffffffu, mc0, 2));
        mc1 = fminf(mc1, __shfl_xor_sync(0xffffffffu, mc1, 1));
        mc1 = fminf(mc1, __shfl_xor_sync(0xffffffffu, mc1, 2));
        const float mn0 = fminf(m0, mc0), mn1 = fminf(m1, mc1);
        if (__any_sync(0xffffffffu, (mn0 < m0) | (mn1 < m1))) {
            const float sc0 = ex2(mn0 - m0), sc1 = ex2(mn1 - m1);
            l0 *= sc0;  l1 *= sc1;
            #pragma unroll
            for (int nb = 0; nb < 8; nb++) {
                O[nb * 4 + 0] *= sc0;  O[nb * 4 + 1] *= sc0;
                O[nb * 4 + 2] *= sc1;  O[nb * 4 + 3] *= sc1;
            }
            m0 = mn0;  m1 = mn1;
        }

        // P = exp2(m - T) computed in f16x2 — results ARE the PV fragments
        uint32_t P0[8], P1[8];
        #pragma unroll
        for (int nb = 0; nb < 8; nb++) {
            P0[nb] = ex2h2(packh(m0 - S[nb * 4 + 0], m0 - S[nb * 4 + 1]));
            P1[nb] = ex2h2(packh(m1 - S[nb * 4 + 2], m1 - S[nb * 4 + 3]));
        }
        {   // row sums via f16x2 trees
            uint32_t s0 = hadd2u(hadd2u(hadd2u(P0[0], P0[1]), hadd2u(P0[2], P0[3])),
                                 hadd2u(hadd2u(P0[4], P0[5]), hadd2u(P0[6], P0[7])));
            uint32_t s1 = hadd2u(hadd2u(hadd2u(P1[0], P1[1]), hadd2u(P1[2], P1[3])),
                                 hadd2u(hadd2u(P1[4], P1[5]), hadd2u(P1[6], P1[7])));
            __half2 h0 = *(__half2*)&s0, h1 = *(__half2*)&s1;
            l0 += __low2float(h0) + __high2float(h0);
            l1 += __low2float(h1) + __high2float(h1);
        }

        // ---- O += P @ V (f16) ----
        #pragma unroll
        for (int kb = 0; kb < 4; kb++) {
            uint32_t pk0 = P0[2 * kb],     pk1 = P1[2 * kb];
            uint32_t pk2 = P0[2 * kb + 1], pk3 = P1[2 * kb + 1];
            #pragma unroll
            for (int c = 0; c < 4; c++) {
                uint32_t off = SWZ((uint32_t)((kb * 16 + vrow) * 128 + c * 32 + vb16));
                uint32_t f0, f1, f2, f3;
                LDSM4T(f0, f1, f2, f3, kb_ + off);
                mma16816r(O + (2 * c) * 4,     pk0, pk1, pk2, pk3, f0, f1);
                mma16816r(O + (2 * c + 1) * 4, pk0, pk1, pk2, pk3, f2, f3);
            }
        }

        CP_WAIT0();
        __syncthreads();
    }

    // ---- epilogue ----
    l0 += __shfl_xor_sync(0xffffffffu, l0, 1);
    l0 += __shfl_xor_sync(0xffffffffu, l0, 2);
    l1 += __shfl_xor_sync(0xffffffffu, l1, 1);
    l1 += __shfl_xor_sync(0xffffffffu, l1, 2);
    const float i0 = 0.1f / l0, i1 = 0.1f / l1;
    const int r0 = blockIdx.x * TM + wid * 16 + (lane >> 2);
    const int r1 = r0 + 8;
    const int cb = (lane & 3) * 2;
    #pragma unroll
    for (int nb = 0; nb < 8; nb++) {
        const int col = nb * 8 + cb;
        float2 pv0 = *(const float2*)(p + (size_t)r0 * D_DIM + col);
        float2 pv1 = *(const float2*)(p + (size_t)r1 * D_DIM + col);
        float2 o0, o1;
        o0.x = 0.9f * pv0.x + O[nb * 4 + 0] * i0;
        o0.y = 0.9f * pv0.y + O[nb * 4 + 1] * i0;
        o1.x = 0.9f * pv1.x + O[nb * 4 + 2] * i1;
        o1.y = 0.9f * pv1.y + O[nb * 4 + 3] * i1;
        *(float2*)(out + (size_t)r0 * D_DIM + col) = o0;
        *(float2*)(out + (size_t)r1 * D_DIM + col) = o1;
    }
}

extern "C" void kernel_launch(void* const* d_in, const int* in_sizes, int n_in,
                              void* d_out, int out_size) {
    const float* p = (const float*)d_in[0];
    float* out = (float*)d_out;
    const int n = in_sizes[0];
    const int N = n / D_DIM;
    prep_kernel<<<(n / 2 + 255) / 256, 256>>>(p, n);
    attn_kernel<<<N / TM, NTH>>>(p, out, N);
}

// round 9
// speedup vs baseline: 1.2496x; 1.2496x over previous
#include <cuda_runtime.h>
#include <cuda_fp16.h>
#include <cstdint>

// out = 0.9*p + 0.1 * softmax(-4 p p^T) p    N=16384, D=64, fp32
// FA2 flash attention, f16 2-pass QK (QhKh + QhKl), f16 PV.
// 8 warps/CTA: warps 0-3 keys [0,32) of each tile, warps 4-7 keys [32,64).

#define D_DIM 64
#define TM    64
#define TN    64
#define NTH   256
#define PN    (16384*64)
#define QSCALE 5.770780163555854f   // 4*log2(e)

__device__ __half g_qh[PN];   // fp16(QSCALE*p)
__device__ __half g_ph[PN];   // fp16(p)       (K hi / V)
__device__ __half g_pl[PN];   // p - fp16(p)   (K lo)

__device__ __forceinline__ uint32_t smem_u32(const void* p) {
    uint32_t a;
    asm("{ .reg .u64 t; cvta.to.shared.u64 t, %1; cvt.u32.u64 %0, t; }" : "=r"(a) : "l"(p));
    return a;
}
#define SWZ(x) ((x) ^ (((x) >> 3) & 0x70))

#define CP16(dst, src) asm volatile("cp.async.ca.shared.global [%0], [%1], 16;" :: "r"(dst), "l"(src))
#define CP_COMMIT()    asm volatile("cp.async.commit_group;" ::: "memory")
#define CP_WAIT0()     asm volatile("cp.async.wait_group 0;" ::: "memory")

#define LDSM4(r0, r1, r2, r3, a) \
    asm volatile("ldmatrix.sync.aligned.m8n8.x4.shared.b16 {%0,%1,%2,%3}, [%4];" \
        : "=r"(r0), "=r"(r1), "=r"(r2), "=r"(r3) : "r"(a))
#define LDSM4T(r0, r1, r2, r3, a) \
    asm volatile("ldmatrix.sync.aligned.m8n8.x4.trans.shared.b16 {%0,%1,%2,%3}, [%4];" \
        : "=r"(r0), "=r"(r1), "=r"(r2), "=r"(r3) : "r"(a))

__device__ __forceinline__ void mma16816(float* c, const uint32_t a[4], uint32_t b0, uint32_t b1) {
    asm volatile("mma.sync.aligned.m16n8k16.row.col.f32.f16.f16.f32 "
        "{%0,%1,%2,%3},{%4,%5,%6,%7},{%8,%9},{%0,%1,%2,%3};"
        : "+f"(c[0]), "+f"(c[1]), "+f"(c[2]), "+f"(c[3])
        : "r"(a[0]), "r"(a[1]), "r"(a[2]), "r"(a[3]), "r"(b0), "r"(b1));
}
__device__ __forceinline__ void mma16816r(float* c, uint32_t a0, uint32_t a1, uint32_t a2, uint32_t a3,
                                          uint32_t b0, uint32_t b1) {
    asm volatile("mma.sync.aligned.m16n8k16.row.col.f32.f16.f16.f32 "
        "{%0,%1,%2,%3},{%4,%5,%6,%7},{%8,%9},{%0,%1,%2,%3};"
        : "+f"(c[0]), "+f"(c[1]), "+f"(c[2]), "+f"(c[3])
        : "r"(a0), "r"(a1), "r"(a2), "r"(a3), "r"(b0), "r"(b1));
}
__device__ __forceinline__ float ex2(float x) {
    float r; asm("ex2.approx.ftz.f32 %0, %1;" : "=f"(r) : "f"(x)); return r;
}
__device__ __forceinline__ uint32_t packh(float lo, float hi) {
    uint32_t r; asm("cvt.rn.f16x2.f32 %0, %2, %1;" : "=r"(r) : "f"(lo), "f"(hi)); return r;
}
__device__ __forceinline__ uint32_t ex2h2(uint32_t x) {
    uint32_t r; asm("ex2.approx.f16x2 %0, %1;" : "=r"(r) : "r"(x)); return r;
}
__device__ __forceinline__ uint32_t hadd2u(uint32_t a, uint32_t b) {
    uint32_t r; asm("add.rn.f16x2 %0, %1, %2;" : "=r"(r) : "r"(a), "r"(b)); return r;
}

__global__ void prep_kernel(const float* __restrict__ p, int n) {
    int i = blockIdx.x * blockDim.x + threadIdx.x;
    if (i < n) {
        float x = p[i];
        __half h = __float2half_rn(x);
        g_ph[i] = h;
        g_pl[i] = __float2half_rn(x - __half2float(h));
        g_qh[i] = __float2half_rn(QSCALE * x);
    }
}

__global__ void __launch_bounds__(NTH, 2)
attn_kernel(const float* __restrict__ p, float* __restrict__ out, int N) {
    __shared__ __align__(128) char sK[2][16384];   // Kh(8K)+Kl(8K), double buffered
    __shared__ __align__(128) char sQ[8192];       // Qh only

    const int tid  = threadIdx.x;
    const int wid  = tid >> 5;
    const int lane = tid & 31;
    const int half = wid >> 2;          // key half of the tile
    const int wrow = wid & 3;           // row group (16 rows)
    const int NT   = N / TN;
    const uint32_t kbase[2] = { smem_u32(sK[0]), smem_u32(sK[1]) };
    const uint32_t qbase    = smem_u32(sQ);

    {   // stage Qh (512 chunks) and K tile 0 hi+lo (512 chunks each)
        const char* sqh = (const char*)g_qh;
        const char* sph = (const char*)g_ph;
        const char* spl = (const char*)g_pl;
        const size_t qoff = (size_t)blockIdx.x * 8192;
        #pragma unroll
        for (int r = 0; r < 2; r++) {
            int c = tid + r * NTH;                 // 0..511
            uint32_t sw = SWZ(c * 16);
            CP16(qbase + sw,           sqh + qoff + c * 16);
            CP16(kbase[0] + sw,        sph + c * 16);
            CP16(kbase[0] + 8192 + sw, spl + c * 16);
        }
        CP_COMMIT();
        CP_WAIT0();
        __syncthreads();
    }

    // Q hi fragments (persistent)
    uint32_t qh[4][4];
    {
        const int qrow = wrow * 16 + (lane & 7) + ((lane >> 3) & 1) * 8;
        const int qb16 = ((lane >> 4) & 1) * 16;
        #pragma unroll
        for (int kb = 0; kb < 4; kb++) {
            uint32_t off = SWZ((uint32_t)(qrow * 128 + kb * 32 + qb16));
            LDSM4(qh[kb][0], qh[kb][1], qh[kb][2], qh[kb][3], qbase + off);
        }
    }

    float O[32];
    #pragma unroll
    for (int i = 0; i < 32; i++) O[i] = 0.f;
    float m0 = 1e30f, m1 = 1e30f, l0 = 0.f, l1 = 0.f;   // running MIN of T

    const uint32_t koffA = (uint32_t)((lane & 7) * 128 + (lane >> 3) * 16);
    const int nbase = half * 4;                         // n-block base (8 keys each)
    const int vrow  = (lane & 7) + ((lane >> 3) & 1) * 8;
    const uint32_t vb16 = ((lane >> 4) & 1) * 16;

    const char* sph = (const char*)g_ph;
    const char* spl = (const char*)g_pl;

    for (int t = 0; t < NT; t++) {
        const uint32_t kb_ = kbase[t & 1];

        if (t + 1 < NT) {
            const uint32_t nb_ = kbase[(t + 1) & 1];
            const size_t src = (size_t)(t + 1) * 8192;
            #pragma unroll
            for (int r = 0; r < 2; r++) {
                int c = tid + r * NTH;             // 0..511
                uint32_t sw = SWZ(c * 16);
                CP16(nb_ + sw,        sph + src + c * 16);
                CP16(nb_ + 8192 + sw, spl + src + c * 16);
            }
        }
        CP_COMMIT();

        // ---- T = QhKh + QhKl over this warp's 32 keys ----
        float S[16];
        #pragma unroll
        for (int i = 0; i < 16; i++) S[i] = 0.f;
        #pragma unroll
        for (int c = 0; c < 2; c++) {
            #pragma unroll
            for (int j = 0; j < 4; j++) {
                uint32_t off = SWZ((uint32_t)((nbase + j) * 1024 + c * 64) + koffA);
                uint32_t f0, f1, f2, f3, g0, g1, g2, g3;
                LDSM4(f0, f1, f2, f3, kb_ + off);            // Kh
                mma16816(S + j * 4, qh[2 * c],     f0, f1);
                mma16816(S + j * 4, qh[2 * c + 1], f2, f3);
                LDSM4(g0, g1, g2, g3, kb_ + 8192 + off);     // Kl
                mma16816(S + j * 4, qh[2 * c],     g0, g1);
                mma16816(S + j * 4, qh[2 * c + 1], g2, g3);
            }
        }

        // ---- online softmax (logit = -T, track min), balanced trees ----
        float mc0 = fminf(fminf(fminf(S[0], S[1]),  fminf(S[4], S[5])),
                          fminf(fminf(S[8], S[9]),  fminf(S[12], S[13])));
        float mc1 = fminf(fminf(fminf(S[2], S[3]),  fminf(S[6], S[7])),
                          fminf(fminf(S[10], S[11]), fminf(S[14], S[15])));
        mc0 = fminf(mc0, __shfl_xor_sync(0xffffffffu, mc0, 1));
        mc0 = fminf(mc0, __shfl_xor_sync(0xffffffffu, mc0, 2));
        mc1 = fminf(mc1, __shfl_xor_sync(0xffffffffu, mc1, 1));
        mc1 = fminf(mc1, __shfl_xor_sync(0xffffffffu, mc1, 2));
        const float mn0 = fminf(m0, mc0), mn1 = fminf(m1, mc1);
        if (__any_sync(0xffffffffu, (mn0 < m0) | (mn1 < m1))) {
            const float sc0 = ex2(mn0 - m0), sc1 = ex2(mn1 - m1);
            l0 *= sc0;  l1 *= sc1;
            #pragma unroll
            for (int j = 0; j < 8; j++) {
                O[j * 4 + 0] *= sc0;  O[j * 4 + 1] *= sc0;
                O[j * 4 + 2] *= sc1;  O[j * 4 + 3] *= sc1;
            }
            m0 = mn0;  m1 = mn1;
        }

        // P = exp2(m - T) in f16x2 — these ARE the PV A-fragments
        uint32_t P0[4], P1[4];
        #pragma unroll
        for (int j = 0; j < 4; j++) {
            P0[j] = ex2h2(packh(m0 - S[j * 4 + 0], m0 - S[j * 4 + 1]));
            P1[j] = ex2h2(packh(m1 - S[j * 4 + 2], m1 - S[j * 4 + 3]));
        }
        {
            uint32_t s0 = hadd2u(hadd2u(P0[0], P0[1]), hadd2u(P0[2], P0[3]));
            uint32_t s1 = hadd2u(hadd2u(P1[0], P1[1]), hadd2u(P1[2], P1[3]));
            __half2 h0 = *(__half2*)&s0, h1 = *(__half2*)&s1;
            l0 += __low2float(h0) + __high2float(h0);
            l1 += __low2float(h1) + __high2float(h1);
        }

        // ---- O += P @ V (f16, V = Kh tile) ----
        #pragma unroll
        for (int kk = 0; kk < 2; kk++) {
            const int kbg = half * 2 + kk;
            uint32_t pk0 = P0[2 * kk],     pk1 = P1[2 * kk];
            uint32_t pk2 = P0[2 * kk + 1], pk3 = P1[2 * kk + 1];
            #pragma unroll
            for (int c = 0; c < 4; c++) {
                uint32_t off = SWZ((uint32_t)((kbg * 16 + vrow) * 128 + c * 32 + vb16));
                uint32_t f0, f1, f2, f3;
                LDSM4T(f0, f1, f2, f3, kb_ + off);
                mma16816r(O + (2 * c) * 4,     pk0, pk1, pk2, pk3, f0, f1);
                mma16816r(O + (2 * c + 1) * 4, pk0, pk1, pk2, pk3, f2, f3);
            }
        }

        CP_WAIT0();
        __syncthreads();
    }

    // ---- merge the two key-half softmax states (warp w <-> w^4) ----
    float* Ob = (float*)sK;                 // [64][66] f32 overlay (17KB < 32KB)
    float* Lb = Ob + 64 * 66;               // [64]
    float* Mx = Lb + 64;                    // [8][16]

    l0 += __shfl_xor_sync(0xffffffffu, l0, 1);
    l0 += __shfl_xor_sync(0xffffffffu, l0, 2);
    l1 += __shfl_xor_sync(0xffffffffu, l1, 1);
    l1 += __shfl_xor_sync(0xffffffffu, l1, 2);

    const int rq = lane >> 2;               // row within 16-group (0..7), +8 for group1
    if ((lane & 3) == 0) {
        Mx[wid * 16 + rq]     = m0;
        Mx[wid * 16 + 8 + rq] = m1;
    }
    __syncthreads();
    {
        const float mp0 = Mx[(wid ^ 4) * 16 + rq];
        const float mp1 = Mx[(wid ^ 4) * 16 + 8 + rq];
        const float ms0 = fminf(m0, mp0), ms1 = fminf(m1, mp1);
        const float s0 = ex2(ms0 - m0), s1 = ex2(ms1 - m1);
        l0 *= s0;  l1 *= s1;
        #pragma unroll
        for (int j = 0; j < 8; j++) {
            O[j * 4 + 0] *= s0;  O[j * 4 + 1] *= s0;
            O[j * 4 + 2] *= s1;  O[j * 4 + 3] *= s1;
        }
    }
    const int rb = wrow * 16 + rq;
    const int cb = (lane & 3) * 2;
    if (half == 0) {
        #pragma unroll
        for (int j = 0; j < 8; j++) {
            Ob[rb * 66 + j * 8 + cb]           = O[j * 4 + 0];
            Ob[rb * 66 + j * 8 + cb + 1]       = O[j * 4 + 1];
            Ob[(rb + 8) * 66 + j * 8 + cb]     = O[j * 4 + 2];
            Ob[(rb + 8) * 66 + j * 8 + cb + 1] = O[j * 4 + 3];
        }
        if ((lane & 3) == 0) { Lb[rb] = l0; Lb[rb + 8] = l1; }
    }
    __syncthreads();
    if (half == 1) {
        l0 += Lb[rb];
        l1 += Lb[rb + 8];
        const float i0 = 0.1f / l0, i1 = 0.1f / l1;
        const int r0 = blockIdx.x * TM + rb;
        const int r1 = r0 + 8;
        #pragma unroll
        for (int j = 0; j < 8; j++) {
            const int col = j * 8 + cb;
            float2 pv0 = *(const float2*)(p + (size_t)r0 * D_DIM + col);
            float2 pv1 = *(const float2*)(p + (size_t)r1 * D_DIM + col);
            float2 o0, o1;
            o0.x = 0.9f * pv0.x + (O[j * 4 + 0] + Ob[rb * 66 + col])           * i0;
            o0.y = 0.9f * pv0.y + (O[j * 4 + 1] + Ob[rb * 66 + col + 1])       * i0;
            o1.x = 0.9f * pv1.x + (O[j * 4 + 2] + Ob[(rb + 8) * 66 + col])     * i1;
            o1.y = 0.9f * pv1.y + (O[j * 4 + 3] + Ob[(rb + 8) * 66 + col + 1]) * i1;
            *(float2*)(out + (size_t)r0 * D_DIM + col) = o0;
            *(float2*)(out + (size_t)r1 * D_DIM + col) = o1;
        }
    }
}

extern "C" void kernel_launch(void* const* d_in, const int* in_sizes, int n_in,
                              void* d_out, int out_size) {
    const float* p = (const float*)d_in[0];
    float* out = (float*)d_out;
    const int n = in_sizes[0];
    const int N = n / D_DIM;
    prep_kernel<<<(n + 255) / 256, 256>>>(p, n);
    attn_kernel<<<N / TM, NTH>>>(p, out, N);
}

// round 10
// speedup vs baseline: 1.2497x; 1.0001x over previous
#include <cuda_runtime.h>
#include <cuda_fp16.h>
#include <cstdint>

// out = 0.9*p + 0.1 * softmax(-4 p p^T) p    N=16384, D=64, fp32
// FA2 flash attention, f16 2-pass QK (QhKh + QhKl), f16 PV.
// 8 warps/CTA: warps 0-3 keys [0,32) of each tile, warps 4-7 keys [32,64).

#define D_DIM 64
#define TM    64
#define TN    64
#define NTH   256
#define PN    (16384*64)
#define QSCALE 5.770780163555854f   // 4*log2(e)

__device__ __half g_qh[PN];   // fp16(QSCALE*p)
__device__ __half g_ph[PN];   // fp16(p)       (K hi / V)
__device__ __half g_pl[PN];   // p - fp16(p)   (K lo)

__device__ __forceinline__ uint32_t smem_u32(const void* p) {
    uint32_t a;
    asm("{ .reg .u64 t; cvta.to.shared.u64 t, %1; cvt.u32.u64 %0, t; }" : "=r"(a) : "l"(p));
    return a;
}
#define SWZ(x) ((x) ^ (((x) >> 3) & 0x70))

#define CP16(dst, src) asm volatile("cp.async.ca.shared.global [%0], [%1], 16;" :: "r"(dst), "l"(src))
#define CP_COMMIT()    asm volatile("cp.async.commit_group;" ::: "memory")
#define CP_WAIT0()     asm volatile("cp.async.wait_group 0;" ::: "memory")

#define LDSM4(r0, r1, r2, r3, a) \
    asm volatile("ldmatrix.sync.aligned.m8n8.x4.shared.b16 {%0,%1,%2,%3}, [%4];" \
        : "=r"(r0), "=r"(r1), "=r"(r2), "=r"(r3) : "r"(a))
#define LDSM4T(r0, r1, r2, r3, a) \
    asm volatile("ldmatrix.sync.aligned.m8n8.x4.trans.shared.b16 {%0,%1,%2,%3}, [%4];" \
        : "=r"(r0), "=r"(r1), "=r"(r2), "=r"(r3) : "r"(a))

__device__ __forceinline__ void mma16816(float* c, const uint32_t a[4], uint32_t b0, uint32_t b1) {
    asm volatile("mma.sync.aligned.m16n8k16.row.col.f32.f16.f16.f32 "
        "{%0,%1,%2,%3},{%4,%5,%6,%7},{%8,%9},{%0,%1,%2,%3};"
        : "+f"(c[0]), "+f"(c[1]), "+f"(c[2]), "+f"(c[3])
        : "r"(a[0]), "r"(a[1]), "r"(a[2]), "r"(a[3]), "r"(b0), "r"(b1));
}
__device__ __forceinline__ void mma16816r(float* c, uint32_t a0, uint32_t a1, uint32_t a2, uint32_t a3,
                                          uint32_t b0, uint32_t b1) {
    asm volatile("mma.sync.aligned.m16n8k16.row.col.f32.f16.f16.f32 "
        "{%0,%1,%2,%3},{%4,%5,%6,%7},{%8,%9},{%0,%1,%2,%3};"
        : "+f"(c[0]), "+f"(c[1]), "+f"(c[2]), "+f"(c[3])
        : "r"(a0), "r"(a1), "r"(a2), "r"(a3), "r"(b0), "r"(b1));
}
__device__ __forceinline__ float ex2(float x) {
    float r; asm("ex2.approx.ftz.f32 %0, %1;" : "=f"(r) : "f"(x)); return r;
}
__device__ __forceinline__ uint32_t packh(float lo, float hi) {
    uint32_t r; asm("cvt.rn.f16x2.f32 %0, %2, %1;" : "=r"(r) : "f"(lo), "f"(hi)); return r;
}
__device__ __forceinline__ uint32_t ex2h2(uint32_t x) {
    uint32_t r; asm("ex2.approx.f16x2 %0, %1;" : "=r"(r) : "r"(x)); return r;
}
__device__ __forceinline__ uint32_t hadd2u(uint32_t a, uint32_t b) {
    uint32_t r; asm("add.rn.f16x2 %0, %1, %2;" : "=r"(r) : "r"(a), "r"(b)); return r;
}

__global__ void prep_kernel(const float* __restrict__ p, int n) {
    int i = blockIdx.x * blockDim.x + threadIdx.x;
    if (i < n) {
        float x = p[i];
        __half h = __float2half_rn(x);
        g_ph[i] = h;
        g_pl[i] = __float2half_rn(x - __half2float(h));
        g_qh[i] = __float2half_rn(QSCALE * x);
    }
}

__global__ void __launch_bounds__(NTH, 2)
attn_kernel(const float* __restrict__ p, float* __restrict__ out, int N) {
    __shared__ __align__(128) char sK[2][16384];   // Kh(8K)+Kl(8K), double buffered
    __shared__ __align__(128) char sQ[8192];       // Qh only

    const int tid  = threadIdx.x;
    const int wid  = tid >> 5;
    const int lane = tid & 31;
    const int half = wid >> 2;          // key half of the tile
    const int wrow = wid & 3;           // row group (16 rows)
    const int NT   = N / TN;
    const uint32_t kbase[2] = { smem_u32(sK[0]), smem_u32(sK[1]) };
    const uint32_t qbase    = smem_u32(sQ);

    {   // stage Qh (512 chunks) and K tile 0 hi+lo (512 chunks each)
        const char* sqh = (const char*)g_qh;
        const char* sph = (const char*)g_ph;
        const char* spl = (const char*)g_pl;
        const size_t qoff = (size_t)blockIdx.x * 8192;
        #pragma unroll
        for (int r = 0; r < 2; r++) {
            int c = tid + r * NTH;                 // 0..511
            uint32_t sw = SWZ(c * 16);
            CP16(qbase + sw,           sqh + qoff + c * 16);
            CP16(kbase[0] + sw,        sph + c * 16);
            CP16(kbase[0] + 8192 + sw, spl + c * 16);
        }
        CP_COMMIT();
        CP_WAIT0();
        __syncthreads();
    }

    // Q hi fragments (persistent)
    uint32_t qh[4][4];
    {
        const int qrow = wrow * 16 + (lane & 7) + ((lane >> 3) & 1) * 8;
        const int qb16 = ((lane >> 4) & 1) * 16;
        #pragma unroll
        for (int kb = 0; kb < 4; kb++) {
            uint32_t off = SWZ((uint32_t)(qrow * 128 + kb * 32 + qb16));
            LDSM4(qh[kb][0], qh[kb][1], qh[kb][2], qh[kb][3], qbase + off);
        }
    }

    float O[32];
    #pragma unroll
    for (int i = 0; i < 32; i++) O[i] = 0.f;
    float m0 = 1e30f, m1 = 1e30f, l0 = 0.f, l1 = 0.f;   // running MIN of T

    const uint32_t koffA = (uint32_t)((lane & 7) * 128 + (lane >> 3) * 16);
    const int nbase = half * 4;                         // n-block base (8 keys each)
    const int vrow  = (lane & 7) + ((lane >> 3) & 1) * 8;
    const uint32_t vb16 = ((lane >> 4) & 1) * 16;

    const char* sph = (const char*)g_ph;
    const char* spl = (const char*)g_pl;

    for (int t = 0; t < NT; t++) {
        const uint32_t kb_ = kbase[t & 1];

        if (t + 1 < NT) {
            const uint32_t nb_ = kbase[(t + 1) & 1];
            const size_t src = (size_t)(t + 1) * 8192;
            #pragma unroll
            for (int r = 0; r < 2; r++) {
                int c = tid + r * NTH;             // 0..511
                uint32_t sw = SWZ(c * 16);
                CP16(nb_ + sw,        sph + src + c * 16);
                CP16(nb_ + 8192 + sw, spl + src + c * 16);
            }
        }
        CP_COMMIT();

        // ---- T = QhKh + QhKl over this warp's 32 keys ----
        float S[16];
        #pragma unroll
        for (int i = 0; i < 16; i++) S[i] = 0.f;
        #pragma unroll
        for (int c = 0; c < 2; c++) {
            #pragma unroll
            for (int j = 0; j < 4; j++) {
                uint32_t off = SWZ((uint32_t)((nbase + j) * 1024 + c * 64) + koffA);
                uint32_t f0, f1, f2, f3, g0, g1, g2, g3;
                LDSM4(f0, f1, f2, f3, kb_ + off);            // Kh
                mma16816(S + j * 4, qh[2 * c],     f0, f1);
                mma16816(S + j * 4, qh[2 * c + 1], f2, f3);
                LDSM4(g0, g1, g2, g3, kb_ + 8192 + off);     // Kl
                mma16816(S + j * 4, qh[2 * c],     g0, g1);
                mma16816(S + j * 4, qh[2 * c + 1], g2, g3);
            }
        }

        // ---- online softmax (logit = -T, track min), balanced trees ----
        float mc0 = fminf(fminf(fminf(S[0], S[1]),  fminf(S[4], S[5])),
                          fminf(fminf(S[8], S[9]),  fminf(S[12], S[13])));
        float mc1 = fminf(fminf(fminf(S[2], S[3]),  fminf(S[6], S[7])),
                          fminf(fminf(S[10], S[11]), fminf(S[14], S[15])));
        mc0 = fminf(mc0, __shfl_xor_sync(0xffffffffu, mc0, 1));
        mc0 = fminf(mc0, __shfl_xor_sync(0xffffffffu, mc0, 2));
        mc1 = fminf(mc1, __shfl_xor_sync(0xffffffffu, mc1, 1));
        mc1 = fminf(mc1, __shfl_xor_sync(0xffffffffu, mc1, 2));
        const float mn0 = fminf(m0, mc0), mn1 = fminf(m1, mc1);
        if (__any_sync(0xffffffffu, (mn0 < m0) | (mn1 < m1))) {
            const float sc0 = ex2(mn0 - m0), sc1 = ex2(mn1 - m1);
            l0 *= sc0;  l1 *= sc1;
            #pragma unroll
            for (int j = 0; j < 8; j++) {
                O[j * 4 + 0] *= sc0;  O[j * 4 + 1] *= sc0;
                O[j * 4 + 2] *= sc1;  O[j * 4 + 3] *= sc1;
            }
            m0 = mn0;  m1 = mn1;
        }

        // P = exp2(m - T) in f16x2 — these ARE the PV A-fragments
        uint32_t P0[4], P1[4];
        #pragma unroll
        for (int j = 0; j < 4; j++) {
            P0[j] = ex2h2(packh(m0 - S[j * 4 + 0], m0 - S[j * 4 + 1]));
            P1[j] = ex2h2(packh(m1 - S[j * 4 + 2], m1 - S[j * 4 + 3]));
        }
        {
            uint32_t s0 = hadd2u(hadd2u(P0[0], P0[1]), hadd2u(P0[2], P0[3]));
            uint32_t s1 = hadd2u(hadd2u(P1[0], P1[1]), hadd2u(P1[2], P1[3]));
            __half2 h0 = *(__half2*)&s0, h1 = *(__half2*)&s1;
            l0 += __low2float(h0) + __high2float(h0);
            l1 += __low2float(h1) + __high2float(h1);
        }

        // ---- O += P @ V (f16, V = Kh tile) ----
        #pragma unroll
        for (int kk = 0; kk < 2; kk++) {
            const int kbg = half * 2 + kk;
            uint32_t pk0 = P0[2 * kk],     pk1 = P1[2 * kk];
            uint32_t pk2 = P0[2 * kk + 1], pk3 = P1[2 * kk + 1];
            #pragma unroll
            for (int c = 0; c < 4; c++) {
                uint32_t off = SWZ((uint32_t)((kbg * 16 + vrow) * 128 + c * 32 + vb16));
                uint32_t f0, f1, f2, f3;
                LDSM4T(f0, f1, f2, f3, kb_ + off);
                mma16816r(O + (2 * c) * 4,     pk0, pk1, pk2, pk3, f0, f1);
                mma16816r(O + (2 * c + 1) * 4, pk0, pk1, pk2, pk3, f2, f3);
            }
        }

        CP_WAIT0();
        __syncthreads();
    }

    // ---- merge the two key-half softmax states (warp w <-> w^4) ----
    float* Ob = (float*)sK;                 // [64][66] f32 overlay (17KB < 32KB)
    float* Lb = Ob + 64 * 66;               // [64]
    float* Mx = Lb + 64;                    // [8][16]

    l0 += __shfl_xor_sync(0xffffffffu, l0, 1);
    l0 += __shfl_xor_sync(0xffffffffu, l0, 2);
    l1 += __shfl_xor_sync(0xffffffffu, l1, 1);
    l1 += __shfl_xor_sync(0xffffffffu, l1, 2);

    const int rq = lane >> 2;               // row within 16-group (0..7), +8 for group1
    if ((lane & 3) == 0) {
        Mx[wid * 16 + rq]     = m0;
        Mx[wid * 16 + 8 + rq] = m1;
    }
    __syncthreads();
    {
        const float mp0 = Mx[(wid ^ 4) * 16 + rq];
        const float mp1 = Mx[(wid ^ 4) * 16 + 8 + rq];
        const float ms0 = fminf(m0, mp0), ms1 = fminf(m1, mp1);
        const float s0 = ex2(ms0 - m0), s1 = ex2(ms1 - m1);
        l0 *= s0;  l1 *= s1;
        #pragma unroll
        for (int j = 0; j < 8; j++) {
            O[j * 4 + 0] *= s0;  O[j * 4 + 1] *= s0;
            O[j * 4 + 2] *= s1;  O[j * 4 + 3] *= s1;
        }
    }
    const int rb = wrow * 16 + rq;
    const int cb = (lane & 3) * 2;
    if (half == 0) {
        #pragma unroll
        for (int j = 0; j < 8; j++) {
            Ob[rb * 66 + j * 8 + cb]           = O[j * 4 + 0];
            Ob[rb * 66 + j * 8 + cb + 1]       = O[j * 4 + 1];
            Ob[(rb + 8) * 66 + j * 8 + cb]     = O[j * 4 + 2];
            Ob[(rb + 8) * 66 + j * 8 + cb + 1] = O[j * 4 + 3];
        }
        if ((lane & 3) == 0) { Lb[rb] = l0; Lb[rb + 8] = l1; }
    }
    __syncthreads();
    if (half == 1) {
        l0 += Lb[rb];
        l1 += Lb[rb + 8];
        const float i0 = 0.1f / l0, i1 = 0.1f / l1;
        const int r0 = blockIdx.x * TM + rb;
        const int r1 = r0 + 8;
        #pragma unroll
        for (int j = 0; j < 8; j++) {
            const int col = j * 8 + cb;
            float2 pv0 = *(const float2*)(p + (size_t)r0 * D_DIM + col);
            float2 pv1 = *(const float2*)(p + (size_t)r1 * D_DIM + col);
            float2 o0, o1;
            o0.x = 0.9f * pv0.x + (O[j * 4 + 0] + Ob[rb * 66 + col])           * i0;
            o0.y = 0.9f * pv0.y + (O[j * 4 + 1] + Ob[rb * 66 + col + 1])       * i0;
            o1.x = 0.9f * pv1.x + (O[j * 4 + 2] + Ob[(rb + 8) * 66 + col])     * i1;
            o1.y = 0.9f * pv1.y + (O[j * 4 + 3] + Ob[(rb + 8) * 66 + col + 1]) * i1;
            *(float2*)(out + (size_t)r0 * D_DIM + col) = o0;
            *(float2*)(out + (size_t)r1 * D_DIM + col) = o1;
        }
    }
}

extern "C" void kernel_launch(void* const* d_in, const int* in_sizes, int n_in,
                              void* d_out, int out_size) {
    const float* p = (const float*)d_in[0];
    float* out = (float*)d_out;
    const int n = in_sizes[0];
    const int N = n / D_DIM;
    prep_kernel<<<(n + 255) / 256, 256>>>(p, n);
    attn_kernel<<<N / TM, NTH>>>(p, out, N);
}

// round 11
// speedup vs baseline: 1.2533x; 1.0029x over previous
#include <cuda_runtime.h>
#include <cuda_fp16.h>
#include <cstdint>

// out = 0.9*p + 0.1 * softmax(-4 p p^T) p    N=16384, D=64, fp32
// FA2 flash attention, f16 2-pass QK (QhKh + QhKl), f16 PV.
// 8 warps/CTA: warps 0-3 keys [0,32) of each tile, warps 4-7 keys [32,64).

#define D_DIM 64
#define TM    64
#define TN    64
#define NTH   256
#define PN    (16384*64)
#define QSCALE 5.770780163555854f   // 4*log2(e)

__device__ __half g_qh[PN];   // fp16(QSCALE*p)
__device__ __half g_ph[PN];   // fp16(p)       (K hi / V)
__device__ __half g_pl[PN];   // p - fp16(p)   (K lo)

__device__ __forceinline__ uint32_t smem_u32(const void* p) {
    uint32_t a;
    asm("{ .reg .u64 t; cvta.to.shared.u64 t, %1; cvt.u32.u64 %0, t; }" : "=r"(a) : "l"(p));
    return a;
}
#define SWZ(x) ((x) ^ (((x) >> 3) & 0x70))

#define CP16(dst, src) asm volatile("cp.async.ca.shared.global [%0], [%1], 16;" :: "r"(dst), "l"(src))
#define CP_COMMIT()    asm volatile("cp.async.commit_group;" ::: "memory")
#define CP_WAIT0()     asm volatile("cp.async.wait_group 0;" ::: "memory")

#define LDSM4(r0, r1, r2, r3, a) \
    asm volatile("ldmatrix.sync.aligned.m8n8.x4.shared.b16 {%0,%1,%2,%3}, [%4];" \
        : "=r"(r0), "=r"(r1), "=r"(r2), "=r"(r3) : "r"(a))
#define LDSM4T(r0, r1, r2, r3, a) \
    asm volatile("ldmatrix.sync.aligned.m8n8.x4.trans.shared.b16 {%0,%1,%2,%3}, [%4];" \
        : "=r"(r0), "=r"(r1), "=r"(r2), "=r"(r3) : "r"(a))

__device__ __forceinline__ void mma16816(float* c, const uint32_t a[4], uint32_t b0, uint32_t b1) {
    asm volatile("mma.sync.aligned.m16n8k16.row.col.f32.f16.f16.f32 "
        "{%0,%1,%2,%3},{%4,%5,%6,%7},{%8,%9},{%0,%1,%2,%3};"
        : "+f"(c[0]), "+f"(c[1]), "+f"(c[2]), "+f"(c[3])
        : "r"(a[0]), "r"(a[1]), "r"(a[2]), "r"(a[3]), "r"(b0), "r"(b1));
}
__device__ __forceinline__ void mma16816r(float* c, uint32_t a0, uint32_t a1, uint32_t a2, uint32_t a3,
                                          uint32_t b0, uint32_t b1) {
    asm volatile("mma.sync.aligned.m16n8k16.row.col.f32.f16.f16.f32 "
        "{%0,%1,%2,%3},{%4,%5,%6,%7},{%8,%9},{%0,%1,%2,%3};"
        : "+f"(c[0]), "+f"(c[1]), "+f"(c[2]), "+f"(c[3])
        : "r"(a0), "r"(a1), "r"(a2), "r"(a3), "r"(b0), "r"(b1));
}
__device__ __forceinline__ float ex2(float x) {
    float r; asm("ex2.approx.ftz.f32 %0, %1;" : "=f"(r) : "f"(x)); return r;
}
__device__ __forceinline__ uint32_t packh(float lo, float hi) {
    uint32_t r; asm("cvt.rn.f16x2.f32 %0, %2, %1;" : "=r"(r) : "f"(lo), "f"(hi)); return r;
}
__device__ __forceinline__ uint32_t ex2h2(uint32_t x) {
    uint32_t r; asm("ex2.approx.f16x2 %0, %1;" : "=r"(r) : "r"(x)); return r;
}
__device__ __forceinline__ uint32_t hadd2u(uint32_t a, uint32_t b) {
    uint32_t r; asm("add.rn.f16x2 %0, %1, %2;" : "=r"(r) : "r"(a), "r"(b)); return r;
}

__global__ void prep_kernel(const float* __restrict__ p, int n) {
    int i = blockIdx.x * blockDim.x + threadIdx.x;
    if (i < n) {
        float x = p[i];
        __half h = __float2half_rn(x);
        g_ph[i] = h;
        g_pl[i] = __float2half_rn(x - __half2float(h));
        g_qh[i] = __float2half_rn(QSCALE * x);
    }
}

__global__ void __launch_bounds__(NTH, 2)
attn_kernel(const float* __restrict__ p, float* __restrict__ out, int N) {
    __shared__ __align__(128) char sK[2][16384];   // Kh(8K)+Kl(8K), double buffered
    __shared__ __align__(128) char sQ[8192];       // Qh only

    const int tid  = threadIdx.x;
    const int wid  = tid >> 5;
    const int lane = tid & 31;
    const int half = wid >> 2;          // key half of the tile
    const int wrow = wid & 3;           // row group (16 rows)
    const int NT   = N / TN;
    const uint32_t kbase[2] = { smem_u32(sK[0]), smem_u32(sK[1]) };
    const uint32_t qbase    = smem_u32(sQ);

    {   // stage Qh (512 chunks) and K tile 0 hi+lo (512 chunks each)
        const char* sqh = (const char*)g_qh;
        const char* sph = (const char*)g_ph;
        const char* spl = (const char*)g_pl;
        const size_t qoff = (size_t)blockIdx.x * 8192;
        #pragma unroll
        for (int r = 0; r < 2; r++) {
            int c = tid + r * NTH;                 // 0..511
            uint32_t sw = SWZ(c * 16);
            CP16(qbase + sw,           sqh + qoff + c * 16);
            CP16(kbase[0] + sw,        sph + c * 16);
            CP16(kbase[0] + 8192 + sw, spl + c * 16);
        }
        CP_COMMIT();
        CP_WAIT0();
        __syncthreads();
    }

    // Q hi fragments (persistent)
    uint32_t qh[4][4];
    {
        const int qrow = wrow * 16 + (lane & 7) + ((lane >> 3) & 1) * 8;
        const int qb16 = ((lane >> 4) & 1) * 16;
        #pragma unroll
        for (int kb = 0; kb < 4; kb++) {
            uint32_t off = SWZ((uint32_t)(qrow * 128 + kb * 32 + qb16));
            LDSM4(qh[kb][0], qh[kb][1], qh[kb][2], qh[kb][3], qbase + off);
        }
    }

    float O[32];
    #pragma unroll
    for (int i = 0; i < 32; i++) O[i] = 0.f;
    float m0 = 1e30f, m1 = 1e30f, l0 = 0.f, l1 = 0.f;   // running MIN of T

    const uint32_t koffA = (uint32_t)((lane & 7) * 128 + (lane >> 3) * 16);
    const int nbase = half * 4;                         // n-block base (8 keys each)
    const int vrow  = (lane & 7) + ((lane >> 3) & 1) * 8;
    const uint32_t vb16 = ((lane >> 4) & 1) * 16;

    const char* sph = (const char*)g_ph;
    const char* spl = (const char*)g_pl;

    for (int t = 0; t < NT; t++) {
        const uint32_t kb_ = kbase[t & 1];

        if (t + 1 < NT) {
            const uint32_t nb_ = kbase[(t + 1) & 1];
            const size_t src = (size_t)(t + 1) * 8192;
            #pragma unroll
            for (int r = 0; r < 2; r++) {
                int c = tid + r * NTH;             // 0..511
                uint32_t sw = SWZ(c * 16);
                CP16(nb_ + sw,        sph + src + c * 16);
                CP16(nb_ + 8192 + sw, spl + src + c * 16);
            }
        }
        CP_COMMIT();

        // ---- T = QhKh + QhKl over this warp's 32 keys ----
        float S[16];
        #pragma unroll
        for (int i = 0; i < 16; i++) S[i] = 0.f;
        #pragma unroll
        for (int c = 0; c < 2; c++) {
            #pragma unroll
            for (int j = 0; j < 4; j++) {
                uint32_t off = SWZ((uint32_t)((nbase + j) * 1024 + c * 64) + koffA);
                uint32_t f0, f1, f2, f3, g0, g1, g2, g3;
                LDSM4(f0, f1, f2, f3, kb_ + off);            // Kh
                mma16816(S + j * 4, qh[2 * c],     f0, f1);
                mma16816(S + j * 4, qh[2 * c + 1], f2, f3);
                LDSM4(g0, g1, g2, g3, kb_ + 8192 + off);     // Kl
                mma16816(S + j * 4, qh[2 * c],     g0, g1);
                mma16816(S + j * 4, qh[2 * c + 1], g2, g3);
            }
        }

        // ---- online softmax (logit = -T, track min), balanced trees ----
        float mc0 = fminf(fminf(fminf(S[0], S[1]),  fminf(S[4], S[5])),
                          fminf(fminf(S[8], S[9]),  fminf(S[12], S[13])));
        float mc1 = fminf(fminf(fminf(S[2], S[3]),  fminf(S[6], S[7])),
                          fminf(fminf(S[10], S[11]), fminf(S[14], S[15])));
        mc0 = fminf(mc0, __shfl_xor_sync(0xffffffffu, mc0, 1));
        mc0 = fminf(mc0, __shfl_xor_sync(0xffffffffu, mc0, 2));
        mc1 = fminf(mc1, __shfl_xor_sync(0xffffffffu, mc1, 1));
        mc1 = fminf(mc1, __shfl_xor_sync(0xffffffffu, mc1, 2));
        const float mn0 = fminf(m0, mc0), mn1 = fminf(m1, mc1);
        if (__any_sync(0xffffffffu, (mn0 < m0) | (mn1 < m1))) {
            const float sc0 = ex2(mn0 - m0), sc1 = ex2(mn1 - m1);
            l0 *= sc0;  l1 *= sc1;
            #pragma unroll
            for (int j = 0; j < 8; j++) {
                O[j * 4 + 0] *= sc0;  O[j * 4 + 1] *= sc0;
                O[j * 4 + 2] *= sc1;  O[j * 4 + 3] *= sc1;
            }
            m0 = mn0;  m1 = mn1;
        }

        // P = exp2(m - T) in f16x2 — these ARE the PV A-fragments
        uint32_t P0[4], P1[4];
        #pragma unroll
        for (int j = 0; j < 4; j++) {
            P0[j] = ex2h2(packh(m0 - S[j * 4 + 0], m0 - S[j * 4 + 1]));
            P1[j] = ex2h2(packh(m1 - S[j * 4 + 2], m1 - S[j * 4 + 3]));
        }
        {
            uint32_t s0 = hadd2u(hadd2u(P0[0], P0[1]), hadd2u(P0[2], P0[3]));
            uint32_t s1 = hadd2u(hadd2u(P1[0], P1[1]), hadd2u(P1[2], P1[3]));
            __half2 h0 = *(__half2*)&s0, h1 = *(__half2*)&s1;
            l0 += __low2float(h0) + __high2float(h0);
            l1 += __low2float(h1) + __high2float(h1);
        }

        // ---- O += P @ V (f16, V = Kh tile) ----
        #pragma unroll
        for (int kk = 0; kk < 2; kk++) {
            const int kbg = half * 2 + kk;
            uint32_t pk0 = P0[2 * kk],     pk1 = P1[2 * kk];
            uint32_t pk2 = P0[2 * kk + 1], pk3 = P1[2 * kk + 1];
            #pragma unroll
            for (int c = 0; c < 4; c++) {
                uint32_t off = SWZ((uint32_t)((kbg * 16 + vrow) * 128 + c * 32 + vb16));
                uint32_t f0, f1, f2, f3;
                LDSM4T(f0, f1, f2, f3, kb_ + off);
                mma16816r(O + (2 * c) * 4,     pk0, pk1, pk2, pk3, f0, f1);
                mma16816r(O + (2 * c + 1) * 4, pk0, pk1, pk2, pk3, f2, f3);
            }
        }

        CP_WAIT0();
        __syncthreads();
    }

    // ---- merge the two key-half softmax states (warp w <-> w^4) ----
    float* Ob = (float*)sK;                 // [64][66] f32 overlay (17KB < 32KB)
    float* Lb = Ob + 64 * 66;               // [64]
    float* Mx = Lb + 64;                    // [8][16]

    l0 += __shfl_xor_sync(0xffffffffu, l0, 1);
    l0 += __shfl_xor_sync(0xffffffffu, l0, 2);
    l1 += __shfl_xor_sync(0xffffffffu, l1, 1);
    l1 += __shfl_xor_sync(0xffffffffu, l1, 2);

    const int rq = lane >> 2;               // row within 16-group (0..7), +8 for group1
    if ((lane & 3) == 0) {
        Mx[wid * 16 + rq]     = m0;
        Mx[wid * 16 + 8 + rq] = m1;
    }
    __syncthreads();
    {
        const float mp0 = Mx[(wid ^ 4) * 16 + rq];
        const float mp1 = Mx[(wid ^ 4) * 16 + 8 + rq];
        const float ms0 = fminf(m0, mp0), ms1 = fminf(m1, mp1);
        const float s0 = ex2(ms0 - m0), s1 = ex2(ms1 - m1);
        l0 *= s0;  l1 *= s1;
        #pragma unroll
        for (int j = 0; j < 8; j++) {
            O[j * 4 + 0] *= s0;  O[j * 4 + 1] *= s0;
            O[j * 4 + 2] *= s1;  O[j * 4 + 3] *= s1;
        }
    }
    const int rb = wrow * 16 + rq;
    const int cb = (lane & 3) * 2;
    if (half == 0) {
        #pragma unroll
        for (int j = 0; j < 8; j++) {
            Ob[rb * 66 + j * 8 + cb]           = O[j * 4 + 0];
            Ob[rb * 66 + j * 8 + cb + 1]       = O[j * 4 + 1];
            Ob[(rb + 8) * 66 + j * 8 + cb]     = O[j * 4 + 2];
            Ob[(rb + 8) * 66 + j * 8 + cb + 1] = O[j * 4 + 3];
        }
        if ((lane & 3) == 0) { Lb[rb] = l0; Lb[rb + 8] = l1; }
    }
    __syncthreads();
    if (half == 1) {
        l0 += Lb[rb];
        l1 += Lb[rb + 8];
        const float i0 = 0.1f / l0, i1 = 0.1f / l1;
        const int r0 = blockIdx.x * TM + rb;
        const int r1 = r0 + 8;
        #pragma unroll
        for (int j = 0; j < 8; j++) {
            const int col = j * 8 + cb;
            float2 pv0 = *(const float2*)(p + (size_t)r0 * D_DIM + col);
            float2 pv1 = *(const float2*)(p + (size_t)r1 * D_DIM + col);
            float2 o0, o1;
            o0.x = 0.9f * pv0.x + (O[j * 4 + 0] + Ob[rb * 66 + col])           * i0;
            o0.y = 0.9f * pv0.y + (O[j * 4 + 1] + Ob[rb * 66 + col + 1])       * i0;
            o1.x = 0.9f * pv1.x + (O[j * 4 + 2] + Ob[(rb + 8) * 66 + col])     * i1;
            o1.y = 0.9f * pv1.y + (O[j * 4 + 3] + Ob[(rb + 8) * 66 + col + 1]) * i1;
            *(float2*)(out + (size_t)r0 * D_DIM + col) = o0;
            *(float2*)(out + (size_t)r1 * D_DIM + col) = o1;
        }
    }
}

extern "C" void kernel_launch(void* const* d_in, const int* in_sizes, int n_in,
                              void* d_out, int out_size) {
    const float* p = (const float*)d_in[0];
    float* out = (float*)d_out;
    const int n = in_sizes[0];
    const int N = n / D_DIM;
    prep_kernel<<<(n + 255) / 256, 256>>>(p, n);
    attn_kernel<<<N / TM, NTH>>>(p, out, N);
}

// round 12
// speedup vs baseline: 1.2756x; 1.0178x over previous
#include <cuda_runtime.h>
#include <cuda_fp16.h>
#include <cstdint>

// out = 0.9*p + 0.1 * softmax(-4 p p^T) p    N=16384, D=64, fp32
// FA2 flash attention, f16 2-pass QK (QhKh + QhKl), f16 PV.
// 8 warps/CTA key-split; software-pipelined: QK(t+1) then PV(t) || softmax(t+1).

#define D_DIM 64
#define TM    64
#define TN    64
#define NTH   256
#define PN    (16384*64)
#define QSCALE 5.770780163555854f   // 4*log2(e)

__device__ __half g_qh[PN];   // fp16(QSCALE*p)
__device__ __half g_ph[PN];   // fp16(p)       (K hi / V)
__device__ __half g_pl[PN];   // p - fp16(p)   (K lo)

__device__ __forceinline__ uint32_t smem_u32(const void* p) {
    uint32_t a;
    asm("{ .reg .u64 t; cvta.to.shared.u64 t, %1; cvt.u32.u64 %0, t; }" : "=r"(a) : "l"(p));
    return a;
}
#define SWZ(x) ((x) ^ (((x) >> 3) & 0x70))

#define CP16(dst, src) asm volatile("cp.async.ca.shared.global [%0], [%1], 16;" :: "r"(dst), "l"(src))
#define CP_COMMIT()    asm volatile("cp.async.commit_group;" ::: "memory")
#define CP_WAIT1()     asm volatile("cp.async.wait_group 1;" ::: "memory")

#define LDSM4(r0, r1, r2, r3, a) \
    asm volatile("ldmatrix.sync.aligned.m8n8.x4.shared.b16 {%0,%1,%2,%3}, [%4];" \
        : "=r"(r0), "=r"(r1), "=r"(r2), "=r"(r3) : "r"(a))
#define LDSM4T(r0, r1, r2, r3, a) \
    asm volatile("ldmatrix.sync.aligned.m8n8.x4.trans.shared.b16 {%0,%1,%2,%3}, [%4];" \
        : "=r"(r0), "=r"(r1), "=r"(r2), "=r"(r3) : "r"(a))

__device__ __forceinline__ void mma16816(float* c, const uint32_t a[4], uint32_t b0, uint32_t b1) {
    asm volatile("mma.sync.aligned.m16n8k16.row.col.f32.f16.f16.f32 "
        "{%0,%1,%2,%3},{%4,%5,%6,%7},{%8,%9},{%0,%1,%2,%3};"
        : "+f"(c[0]), "+f"(c[1]), "+f"(c[2]), "+f"(c[3])
        : "r"(a[0]), "r"(a[1]), "r"(a[2]), "r"(a[3]), "r"(b0), "r"(b1));
}
__device__ __forceinline__ void mma16816r(float* c, uint32_t a0, uint32_t a1, uint32_t a2, uint32_t a3,
                                          uint32_t b0, uint32_t b1) {
    asm volatile("mma.sync.aligned.m16n8k16.row.col.f32.f16.f16.f32 "
        "{%0,%1,%2,%3},{%4,%5,%6,%7},{%8,%9},{%0,%1,%2,%3};"
        : "+f"(c[0]), "+f"(c[1]), "+f"(c[2]), "+f"(c[3])
        : "r"(a0), "r"(a1), "r"(a2), "r"(a3), "r"(b0), "r"(b1));
}
__device__ __forceinline__ float ex2(float x) {
    float r; asm("ex2.approx.ftz.f32 %0, %1;" : "=f"(r) : "f"(x)); return r;
}
__device__ __forceinline__ uint32_t packh(float lo, float hi) {
    uint32_t r; asm("cvt.rn.f16x2.f32 %0, %2, %1;" : "=r"(r) : "f"(lo), "f"(hi)); return r;
}
__device__ __forceinline__ uint32_t ex2h2(uint32_t x) {
    uint32_t r; asm("ex2.approx.f16x2 %0, %1;" : "=r"(r) : "r"(x)); return r;
}
__device__ __forceinline__ uint32_t hadd2u(uint32_t a, uint32_t b) {
    uint32_t r; asm("add.rn.f16x2 %0, %1, %2;" : "=r"(r) : "r"(a), "r"(b)); return r;
}

__global__ void prep_kernel(const float* __restrict__ p, int n) {
    int i = blockIdx.x * blockDim.x + threadIdx.x;
    if (i < n) {
        float x = p[i];
        __half h = __float2half_rn(x);
        g_ph[i] = h;
        g_pl[i] = __float2half_rn(x - __half2float(h));
        g_qh[i] = __float2half_rn(QSCALE * x);
    }
}

__global__ void __launch_bounds__(NTH, 2)
attn_kernel(const float* __restrict__ p, float* __restrict__ out, int N) {
    __shared__ __align__(128) char sK[3][16384];   // 3-deep ring: Kh(8K)+Kl(8K)

    const int tid  = threadIdx.x;
    const int wid  = tid >> 5;
    const int lane = tid & 31;
    const int half = wid >> 2;
    const int wrow = wid & 3;
    const int NT   = N / TN;
    const uint32_t kbase[3] = { smem_u32(sK[0]), smem_u32(sK[1]), smem_u32(sK[2]) };

    const int c0 = tid, c1 = tid + NTH;            // chunk ids 0..511
    const uint32_t sw0 = SWZ(c0 * 16), sw1 = SWZ(c1 * 16);
    const char* sqh = (const char*)g_qh;
    const char* sph = (const char*)g_ph;
    const char* spl = (const char*)g_pl;

    {   // G0: Q (into buf2) + tile0 (buf0);  G1: tile1 (buf1)
        const size_t qoff = (size_t)blockIdx.x * 8192;
        CP16(kbase[2] + sw0,        sqh + qoff + c0 * 16);
        CP16(kbase[2] + sw1,        sqh + qoff + c1 * 16);
        CP16(kbase[0] + sw0,        sph + c0 * 16);
        CP16(kbase[0] + sw1,        sph + c1 * 16);
        CP16(kbase[0] + 8192 + sw0, spl + c0 * 16);
        CP16(kbase[0] + 8192 + sw1, spl + c1 * 16);
        CP_COMMIT();
        CP16(kbase[1] + sw0,        sph + 8192 + c0 * 16);
        CP16(kbase[1] + sw1,        sph + 8192 + c1 * 16);
        CP16(kbase[1] + 8192 + sw0, spl + 8192 + c0 * 16);
        CP16(kbase[1] + 8192 + sw1, spl + 8192 + c1 * 16);
        CP_COMMIT();
        CP_WAIT1();            // G0 done (Q + tile0)
        __syncthreads();
    }

    // Q hi fragments from buf2 (dead after this; tile2 overwrites at t=0)
    uint32_t qh[4][4];
    {
        const int qrow = wrow * 16 + (lane & 7) + ((lane >> 3) & 1) * 8;
        const int qb16 = ((lane >> 4) & 1) * 16;
        #pragma unroll
        for (int kb = 0; kb < 4; kb++) {
            uint32_t off = SWZ((uint32_t)(qrow * 128 + kb * 32 + qb16));
            LDSM4(qh[kb][0], qh[kb][1], qh[kb][2], qh[kb][3], kbase[2] + off);
        }
    }

    const uint32_t koffA = (uint32_t)((lane & 7) * 128 + (lane >> 3) * 16);
    const int nbase = half * 4;
    const int vrow  = (lane & 7) + ((lane >> 3) & 1) * 8;
    const uint32_t vb16 = ((lane >> 4) & 1) * 16;

    float O[32];
    #pragma unroll
    for (int i = 0; i < 32; i++) O[i] = 0.f;
    float m0, m1, l0, l1;
    uint32_t Pc0[4], Pc1[4];

    // ---- QK macro body (writes S from buffer qb_) ----
#define QK_BODY(qb_, S)                                                        \
    {                                                                          \
        _Pragma("unroll")                                                      \
        for (int i = 0; i < 16; i++) S[i] = 0.f;                               \
        _Pragma("unroll")                                                      \
        for (int c = 0; c < 2; c++) {                                          \
            _Pragma("unroll")                                                  \
            for (int j = 0; j < 4; j++) {                                      \
                uint32_t off = SWZ((uint32_t)((nbase + j) * 1024 + c * 64) + koffA); \
                uint32_t f0, f1, f2, f3, g0, g1, g2, g3;                       \
                LDSM4(f0, f1, f2, f3, (qb_) + off);                            \
                mma16816(S + j * 4, qh[2 * c],     f0, f1);                    \
                mma16816(S + j * 4, qh[2 * c + 1], f2, f3);                    \
                LDSM4(g0, g1, g2, g3, (qb_) + 8192 + off);                     \
                mma16816(S + j * 4, qh[2 * c],     g0, g1);                    \
                mma16816(S + j * 4, qh[2 * c + 1], g2, g3);                    \
            }                                                                  \
        }                                                                      \
    }

#define PV_BODY(pb_)                                                           \
    {                                                                          \
        _Pragma("unroll")                                                      \
        for (int kk = 0; kk < 2; kk++) {                                       \
            const int kbg = half * 2 + kk;                                     \
            uint32_t pk0 = Pc0[2 * kk],     pk1 = Pc1[2 * kk];                 \
            uint32_t pk2 = Pc0[2 * kk + 1], pk3 = Pc1[2 * kk + 1];             \
            _Pragma("unroll")                                                  \
            for (int c = 0; c < 4; c++) {                                      \
                uint32_t off = SWZ((uint32_t)((kbg * 16 + vrow) * 128 + c * 32 + vb16)); \
                uint32_t f0, f1, f2, f3;                                       \
                LDSM4T(f0, f1, f2, f3, (pb_) + off);                           \
                mma16816r(O + (2 * c) * 4,     pk0, pk1, pk2, pk3, f0, f1);    \
                mma16816r(O + (2 * c + 1) * 4, pk0, pk1, pk2, pk3, f2, f3);    \
            }                                                                  \
        }                                                                      \
    }

#define MIN_TREES(S, mc0, mc1)                                                 \
    float mc0 = fminf(fminf(fminf(S[0], S[1]),   fminf(S[4], S[5])),           \
                      fminf(fminf(S[8], S[9]),   fminf(S[12], S[13])));        \
    float mc1 = fminf(fminf(fminf(S[2], S[3]),   fminf(S[6], S[7])),           \
                      fminf(fminf(S[10], S[11]), fminf(S[14], S[15])));        \
    mc0 = fminf(mc0, __shfl_xor_sync(0xffffffffu, mc0, 1));                    \
    mc0 = fminf(mc0, __shfl_xor_sync(0xffffffffu, mc0, 2));                    \
    mc1 = fminf(mc1, __shfl_xor_sync(0xffffffffu, mc1, 1));                    \
    mc1 = fminf(mc1, __shfl_xor_sync(0xffffffffu, mc1, 2));

    {   // ---- prologue: QK(0), softmax(0) -> Pc, m, l ----
        float S[16];
        QK_BODY(kbase[0], S);
        MIN_TREES(S, mc0, mc1);
        m0 = mc0;  m1 = mc1;
        #pragma unroll
        for (int j = 0; j < 4; j++) {
            Pc0[j] = ex2h2(packh(m0 - S[j * 4 + 0], m0 - S[j * 4 + 1]));
            Pc1[j] = ex2h2(packh(m1 - S[j * 4 + 2], m1 - S[j * 4 + 3]));
        }
        uint32_t s0 = hadd2u(hadd2u(Pc0[0], Pc0[1]), hadd2u(Pc0[2], Pc0[3]));
        uint32_t s1 = hadd2u(hadd2u(Pc1[0], Pc1[1]), hadd2u(Pc1[2], Pc1[3]));
        __half2 h0 = *(__half2*)&s0, h1 = *(__half2*)&s1;
        l0 = __low2float(h0) + __high2float(h0);
        l1 = __low2float(h1) + __high2float(h1);
    }

    int ib0 = 0, ib1 = 1, ib2 = 2;      // t%3, (t+1)%3, (t+2)%3
    for (int t = 0; t < NT - 1; t++) {
        // prefetch tile t+2 into buf ib2 (readers of ib2 finished last iter)
        if (t + 2 < NT) {
            const uint32_t nb_ = kbase[ib2];
            const char* s1 = sph + (size_t)(t + 2) * 8192;
            const char* s2 = spl + (size_t)(t + 2) * 8192;
            CP16(nb_ + sw0,        s1 + c0 * 16);
            CP16(nb_ + sw1,        s1 + c1 * 16);
            CP16(nb_ + 8192 + sw0, s2 + c0 * 16);
            CP16(nb_ + 8192 + sw1, s2 + c1 * 16);
        }
        CP_COMMIT();
        CP_WAIT1();                 // tile t+1 landed (mine)
        __syncthreads();            // ...and everyone's

        float S[16];
        QK_BODY(kbase[ib1], S);     // QK(t+1)

        MIN_TREES(S, mc0, mc1);
        const float mn0 = fminf(m0, mc0), mn1 = fminf(m1, mc1);
        const bool upd = (mn0 < m0) | (mn1 < m1);
        uint32_t Pn0[4], Pn1[4];
        #pragma unroll
        for (int j = 0; j < 4; j++) {
            Pn0[j] = ex2h2(packh(mn0 - S[j * 4 + 0], mn0 - S[j * 4 + 1]));
            Pn1[j] = ex2h2(packh(mn1 - S[j * 4 + 2], mn1 - S[j * 4 + 3]));
        }

        PV_BODY(kbase[ib0]);        // PV(t) with Pc at scale m(t) — overlaps softmax above

        if (__any_sync(0xffffffffu, upd)) {      // rebase O,l to m(t+1) AFTER PV(t)
            const float sc0 = ex2(mn0 - m0), sc1 = ex2(mn1 - m1);
            l0 *= sc0;  l1 *= sc1;
            #pragma unroll
            for (int j = 0; j < 8; j++) {
                O[j * 4 + 0] *= sc0;  O[j * 4 + 1] *= sc0;
                O[j * 4 + 2] *= sc1;  O[j * 4 + 3] *= sc1;
            }
        }
        m0 = mn0;  m1 = mn1;
        {
            uint32_t s0 = hadd2u(hadd2u(Pn0[0], Pn0[1]), hadd2u(Pn0[2], Pn0[3]));
            uint32_t s1 = hadd2u(hadd2u(Pn1[0], Pn1[1]), hadd2u(Pn1[2], Pn1[3]));
            __half2 h0 = *(__half2*)&s0, h1 = *(__half2*)&s1;
            l0 += __low2float(h0) + __high2float(h0);
            l1 += __low2float(h1) + __high2float(h1);
        }
        #pragma unroll
        for (int j = 0; j < 4; j++) { Pc0[j] = Pn0[j]; Pc1[j] = Pn1[j]; }

        __syncthreads();            // all reads of buf ib0 done (freed for prefetch)
        int tmp = ib0; ib0 = ib1; ib1 = ib2; ib2 = tmp;
    }

    PV_BODY(kbase[ib0]);            // PV(NT-1)

    // ---- merge the two key-half softmax states (warp w <-> w^4) ----
    float* Ob = (float*)sK;                 // [64][66] f32 overlay
    float* Lb = Ob + 64 * 66;               // [64]
    float* Mx = Lb + 64;                    // [8][16]

    l0 += __shfl_xor_sync(0xffffffffu, l0, 1);
    l0 += __shfl_xor_sync(0xffffffffu, l0, 2);
    l1 += __shfl_xor_sync(0xffffffffu, l1, 1);
    l1 += __shfl_xor_sync(0xffffffffu, l1, 2);

    const int rq = lane >> 2;
    __syncthreads();                        // everyone done with PV(NT-1) smem reads
    if ((lane & 3) == 0) {
        Mx[wid * 16 + rq]     = m0;
        Mx[wid * 16 + 8 + rq] = m1;
    }
    __syncthreads();
    {
        const float mp0 = Mx[(wid ^ 4) * 16 + rq];
        const float mp1 = Mx[(wid ^ 4) * 16 + 8 + rq];
        const float ms0 = fminf(m0, mp0), ms1 = fminf(m1, mp1);
        const float s0 = ex2(ms0 - m0), s1 = ex2(ms1 - m1);
        l0 *= s0;  l1 *= s1;
        #pragma unroll
        for (int j = 0; j < 8; j++) {
            O[j * 4 + 0] *= s0;  O[j * 4 + 1] *= s0;
            O[j * 4 + 2] *= s1;  O[j * 4 + 3] *= s1;
        }
    }
    const int rb = wrow * 16 + rq;
    const int cb = (lane & 3) * 2;
    if (half == 0) {
        #pragma unroll
        for (int j = 0; j < 8; j++) {
            Ob[rb * 66 + j * 8 + cb]           = O[j * 4 + 0];
            Ob[rb * 66 + j * 8 + cb + 1]       = O[j * 4 + 1];
            Ob[(rb + 8) * 66 + j * 8 + cb]     = O[j * 4 + 2];
            Ob[(rb + 8) * 66 + j * 8 + cb + 1] = O[j * 4 + 3];
        }
        if ((lane & 3) == 0) { Lb[rb] = l0; Lb[rb + 8] = l1; }
    }
    __syncthreads();
    if (half == 1) {
        l0 += Lb[rb];
        l1 += Lb[rb + 8];
        const float i0 = 0.1f / l0, i1 = 0.1f / l1;
        const int r0 = blockIdx.x * TM + rb;
        const int r1 = r0 + 8;
        #pragma unroll
        for (int j = 0; j < 8; j++) {
            const int col = j * 8 + cb;
            float2 pv0 = *(const float2*)(p + (size_t)r0 * D_DIM + col);
            float2 pv1 = *(const float2*)(p + (size_t)r1 * D_DIM + col);
            float2 o0, o1;
            o0.x = 0.9f * pv0.x + (O[j * 4 + 0] + Ob[rb * 66 + col])           * i0;
            o0.y = 0.9f * pv0.y + (O[j * 4 + 1] + Ob[rb * 66 + col + 1])       * i0;
            o1.x = 0.9f * pv1.x + (O[j * 4 + 2] + Ob[(rb + 8) * 66 + col])     * i1;
            o1.y = 0.9f * pv1.y + (O[j * 4 + 3] + Ob[(rb + 8) * 66 + col + 1]) * i1;
            *(float2*)(out + (size_t)r0 * D_DIM + col) = o0;
            *(float2*)(out + (size_t)r1 * D_DIM + col) = o1;
        }
    }
}

extern "C" void kernel_launch(void* const* d_in, const int* in_sizes, int n_in,
                              void* d_out, int out_size) {
    const float* p = (const float*)d_in[0];
    float* out = (float*)d_out;
    const int n = in_sizes[0];
    const int N = n / D_DIM;
    prep_kernel<<<(n + 255) / 256, 256>>>(p, n);
    attn_kernel<<<N / TM, NTH>>>(p, out, N);
}

// round 13
// speedup vs baseline: 1.8205x; 1.4272x over previous
#include <cuda_runtime.h>
#include <cuda_fp16.h>
#include <cstdint>

// out = 0.9*p + 0.1 * softmax(-4 p p^T) p    N=16384, D=64, fp32
// FA2 flash attention, single-pass f16 QK, f16 PV, key-split 8 warps,
// software-pipelined: QK(t+1) then PV(t) || softmax(t+1). 3-deep K ring.

#define D_DIM 64
#define TM    64
#define TN    64
#define NTH   256
#define PN    (16384*64)
#define QSCALE 5.770780163555854f   // 4*log2(e)

__device__ __half g_qh[PN];   // fp16(QSCALE*p)
__device__ __half g_ph[PN];   // fp16(p)  (K / V)

__device__ __forceinline__ uint32_t smem_u32(const void* p) {
    uint32_t a;
    asm("{ .reg .u64 t; cvta.to.shared.u64 t, %1; cvt.u32.u64 %0, t; }" : "=r"(a) : "l"(p));
    return a;
}
#define SWZ(x) ((x) ^ (((x) >> 3) & 0x70))

#define CP16(dst, src) asm volatile("cp.async.ca.shared.global [%0], [%1], 16;" :: "r"(dst), "l"(src))
#define CP_COMMIT()    asm volatile("cp.async.commit_group;" ::: "memory")
#define CP_WAIT1()     asm volatile("cp.async.wait_group 1;" ::: "memory")

#define LDSM4(r0, r1, r2, r3, a) \
    asm volatile("ldmatrix.sync.aligned.m8n8.x4.shared.b16 {%0,%1,%2,%3}, [%4];" \
        : "=r"(r0), "=r"(r1), "=r"(r2), "=r"(r3) : "r"(a))
#define LDSM4T(r0, r1, r2, r3, a) \
    asm volatile("ldmatrix.sync.aligned.m8n8.x4.trans.shared.b16 {%0,%1,%2,%3}, [%4];" \
        : "=r"(r0), "=r"(r1), "=r"(r2), "=r"(r3) : "r"(a))

__device__ __forceinline__ void mma16816(float* c, const uint32_t a[4], uint32_t b0, uint32_t b1) {
    asm volatile("mma.sync.aligned.m16n8k16.row.col.f32.f16.f16.f32 "
        "{%0,%1,%2,%3},{%4,%5,%6,%7},{%8,%9},{%0,%1,%2,%3};"
        : "+f"(c[0]), "+f"(c[1]), "+f"(c[2]), "+f"(c[3])
        : "r"(a[0]), "r"(a[1]), "r"(a[2]), "r"(a[3]), "r"(b0), "r"(b1));
}
__device__ __forceinline__ void mma16816r(float* c, uint32_t a0, uint32_t a1, uint32_t a2, uint32_t a3,
                                          uint32_t b0, uint32_t b1) {
    asm volatile("mma.sync.aligned.m16n8k16.row.col.f32.f16.f16.f32 "
        "{%0,%1,%2,%3},{%4,%5,%6,%7},{%8,%9},{%0,%1,%2,%3};"
        : "+f"(c[0]), "+f"(c[1]), "+f"(c[2]), "+f"(c[3])
        : "r"(a0), "r"(a1), "r"(a2), "r"(a3), "r"(b0), "r"(b1));
}
__device__ __forceinline__ float ex2(float x) {
    float r; asm("ex2.approx.ftz.f32 %0, %1;" : "=f"(r) : "f"(x)); return r;
}
__device__ __forceinline__ uint32_t packh(float lo, float hi) {
    uint32_t r; asm("cvt.rn.f16x2.f32 %0, %2, %1;" : "=r"(r) : "f"(lo), "f"(hi)); return r;
}
__device__ __forceinline__ uint32_t ex2h2(uint32_t x) {
    uint32_t r; asm("ex2.approx.f16x2 %0, %1;" : "=r"(r) : "r"(x)); return r;
}
__device__ __forceinline__ uint32_t hadd2u(uint32_t a, uint32_t b) {
    uint32_t r; asm("add.rn.f16x2 %0, %1, %2;" : "=r"(r) : "r"(a), "r"(b)); return r;
}

__global__ void prep_kernel(const float* __restrict__ p, int n) {
    int i = blockIdx.x * blockDim.x + threadIdx.x;
    if (i < n) {
        float x = p[i];
        g_ph[i] = __float2half_rn(x);
        g_qh[i] = __float2half_rn(QSCALE * x);
    }
}

__global__ void __launch_bounds__(NTH, 2)
attn_kernel(const float* __restrict__ p, float* __restrict__ out, int N) {
    __shared__ __align__(128) char sK[3][8192];    // 3-deep K ring (Kh only)

    const int tid  = threadIdx.x;
    const int wid  = tid >> 5;
    const int lane = tid & 31;
    const int half = wid >> 2;
    const int wrow = wid & 3;
    const int NT   = N / TN;
    const uint32_t kbase[3] = { smem_u32(sK[0]), smem_u32(sK[1]), smem_u32(sK[2]) };

    const int c0 = tid, c1 = tid + NTH;            // chunk ids 0..511
    const uint32_t sw0 = SWZ(c0 * 16), sw1 = SWZ(c1 * 16);
    const char* sqh = (const char*)g_qh;
    const char* sph = (const char*)g_ph;

    {   // G0: Q (into buf2) + tile0 (buf0);  G1: tile1 (buf1)
        const size_t qoff = (size_t)blockIdx.x * 8192;
        CP16(kbase[2] + sw0, sqh + qoff + c0 * 16);
        CP16(kbase[2] + sw1, sqh + qoff + c1 * 16);
        CP16(kbase[0] + sw0, sph + c0 * 16);
        CP16(kbase[0] + sw1, sph + c1 * 16);
        CP_COMMIT();
        CP16(kbase[1] + sw0, sph + 8192 + c0 * 16);
        CP16(kbase[1] + sw1, sph + 8192 + c1 * 16);
        CP_COMMIT();
        CP_WAIT1();            // G0 done (Q + tile0)
        __syncthreads();
    }

    // Q fragments from buf2 (dead after this; tile2 overwrites at t=0)
    uint32_t qh[4][4];
    {
        const int qrow = wrow * 16 + (lane & 7) + ((lane >> 3) & 1) * 8;
        const int qb16 = ((lane >> 4) & 1) * 16;
        #pragma unroll
        for (int kb = 0; kb < 4; kb++) {
            uint32_t off = SWZ((uint32_t)(qrow * 128 + kb * 32 + qb16));
            LDSM4(qh[kb][0], qh[kb][1], qh[kb][2], qh[kb][3], kbase[2] + off);
        }
    }

    const uint32_t koffA = (uint32_t)((lane & 7) * 128 + (lane >> 3) * 16);
    const int nbase = half * 4;
    const int vrow  = (lane & 7) + ((lane >> 3) & 1) * 8;
    const uint32_t vb16 = ((lane >> 4) & 1) * 16;

    float O[32];
    #pragma unroll
    for (int i = 0; i < 32; i++) O[i] = 0.f;
    float m0, m1, l0, l1;
    uint32_t Pc0[4], Pc1[4];

#define QK_BODY(qb_, S)                                                        \
    {                                                                          \
        _Pragma("unroll")                                                      \
        for (int i = 0; i < 16; i++) S[i] = 0.f;                               \
        _Pragma("unroll")                                                      \
        for (int c = 0; c < 2; c++) {                                          \
            _Pragma("unroll")                                                  \
            for (int j = 0; j < 4; j++) {                                      \
                uint32_t off = SWZ((uint32_t)((nbase + j) * 1024 + c * 64) + koffA); \
                uint32_t f0, f1, f2, f3;                                       \
                LDSM4(f0, f1, f2, f3, (qb_) + off);                            \
                mma16816(S + j * 4, qh[2 * c],     f0, f1);                    \
                mma16816(S + j * 4, qh[2 * c + 1], f2, f3);                    \
            }                                                                  \
        }                                                                      \
    }

#define PV_BODY(pb_)                                                           \
    {                                                                          \
        _Pragma("unroll")                                                      \
        for (int kk = 0; kk < 2; kk++) {                                       \
            const int kbg = half * 2 + kk;                                     \
            uint32_t pk0 = Pc0[2 * kk],     pk1 = Pc1[2 * kk];                 \
            uint32_t pk2 = Pc0[2 * kk + 1], pk3 = Pc1[2 * kk + 1];             \
            _Pragma("unroll")                                                  \
            for (int c = 0; c < 4; c++) {                                      \
                uint32_t off = SWZ((uint32_t)((kbg * 16 + vrow) * 128 + c * 32 + vb16)); \
                uint32_t f0, f1, f2, f3;                                       \
                LDSM4T(f0, f1, f2, f3, (pb_) + off);                           \
                mma16816r(O + (2 * c) * 4,     pk0, pk1, pk2, pk3, f0, f1);    \
                mma16816r(O + (2 * c + 1) * 4, pk0, pk1, pk2, pk3, f2, f3);    \
            }                                                                  \
        }                                                                      \
    }

#define MIN_TREES(S, mc0, mc1)                                                 \
    float mc0 = fminf(fminf(fminf(S[0], S[1]),   fminf(S[4], S[5])),           \
                      fminf(fminf(S[8], S[9]),   fminf(S[12], S[13])));        \
    float mc1 = fminf(fminf(fminf(S[2], S[3]),   fminf(S[6], S[7])),           \
                      fminf(fminf(S[10], S[11]), fminf(S[14], S[15])));        \
    mc0 = fminf(mc0, __shfl_xor_sync(0xffffffffu, mc0, 1));                    \
    mc0 = fminf(mc0, __shfl_xor_sync(0xffffffffu, mc0, 2));                    \
    mc1 = fminf(mc1, __shfl_xor_sync(0xffffffffu, mc1, 1));                    \
    mc1 = fminf(mc1, __shfl_xor_sync(0xffffffffu, mc1, 2));

    {   // ---- prologue: QK(0), softmax(0) ----
        float S[16];
        QK_BODY(kbase[0], S);
        MIN_TREES(S, mc0, mc1);
        m0 = mc0;  m1 = mc1;
        #pragma unroll
        for (int j = 0; j < 4; j++) {
            Pc0[j] = ex2h2(packh(m0 - S[j * 4 + 0], m0 - S[j * 4 + 1]));
            Pc1[j] = ex2h2(packh(m1 - S[j * 4 + 2], m1 - S[j * 4 + 3]));
        }
        uint32_t s0 = hadd2u(hadd2u(Pc0[0], Pc0[1]), hadd2u(Pc0[2], Pc0[3]));
        uint32_t s1 = hadd2u(hadd2u(Pc1[0], Pc1[1]), hadd2u(Pc1[2], Pc1[3]));
        __half2 h0 = *(__half2*)&s0, h1 = *(__half2*)&s1;
        l0 = __low2float(h0) + __high2float(h0);
        l1 = __low2float(h1) + __high2float(h1);
    }

    int ib0 = 0, ib1 = 1, ib2 = 2;
    for (int t = 0; t < NT - 1; t++) {
        if (t + 2 < NT) {
            const uint32_t nb_ = kbase[ib2];
            const char* s1 = sph + (size_t)(t + 2) * 8192;
            CP16(nb_ + sw0, s1 + c0 * 16);
            CP16(nb_ + sw1, s1 + c1 * 16);
        }
        CP_COMMIT();
        CP_WAIT1();                 // tile t+1 landed
        __syncthreads();

        float S[16];
        QK_BODY(kbase[ib1], S);     // QK(t+1)

        MIN_TREES(S, mc0, mc1);
        const float mn0 = fminf(m0, mc0), mn1 = fminf(m1, mc1);
        const bool upd = (mn0 < m0) | (mn1 < m1);
        uint32_t Pn0[4], Pn1[4];
        #pragma unroll
        for (int j = 0; j < 4; j++) {
            Pn0[j] = ex2h2(packh(mn0 - S[j * 4 + 0], mn0 - S[j * 4 + 1]));
            Pn1[j] = ex2h2(packh(mn1 - S[j * 4 + 2], mn1 - S[j * 4 + 3]));
        }

        PV_BODY(kbase[ib0]);        // PV(t) at scale m(t) — overlaps softmax above

        if (__any_sync(0xffffffffu, upd)) {
            const float sc0 = ex2(mn0 - m0), sc1 = ex2(mn1 - m1);
            l0 *= sc0;  l1 *= sc1;
            #pragma unroll
            for (int j = 0; j < 8; j++) {
                O[j * 4 + 0] *= sc0;  O[j * 4 + 1] *= sc0;
                O[j * 4 + 2] *= sc1;  O[j * 4 + 3] *= sc1;
            }
        }
        m0 = mn0;  m1 = mn1;
        {
            uint32_t s0 = hadd2u(hadd2u(Pn0[0], Pn0[1]), hadd2u(Pn0[2], Pn0[3]));
            uint32_t s1 = hadd2u(hadd2u(Pn1[0], Pn1[1]), hadd2u(Pn1[2], Pn1[3]));
            __half2 h0 = *(__half2*)&s0, h1 = *(__half2*)&s1;
            l0 += __low2float(h0) + __high2float(h0);
            l1 += __low2float(h1) + __high2float(h1);
        }
        #pragma unroll
        for (int j = 0; j < 4; j++) { Pc0[j] = Pn0[j]; Pc1[j] = Pn1[j]; }

        __syncthreads();            // all reads of buf ib0 done
        int tmp = ib0; ib0 = ib1; ib1 = ib2; ib2 = tmp;
    }

    PV_BODY(kbase[ib0]);            // PV(NT-1)

    // ---- merge the two key-half softmax states (warp w <-> w^4) ----
    float* Ob = (float*)sK;                 // [64][66] overlay (17.5KB < 24KB)
    float* Lb = Ob + 64 * 66;
    float* Mx = Lb + 64;

    l0 += __shfl_xor_sync(0xffffffffu, l0, 1);
    l0 += __shfl_xor_sync(0xffffffffu, l0, 2);
    l1 += __shfl_xor_sync(0xffffffffu, l1, 1);
    l1 += __shfl_xor_sync(0xffffffffu, l1, 2);

    const int rq = lane >> 2;
    __syncthreads();
    if ((lane & 3) == 0) {
        Mx[wid * 16 + rq]     = m0;
        Mx[wid * 16 + 8 + rq] = m1;
    }
    __syncthreads();
    {
        const float mp0 = Mx[(wid ^ 4) * 16 + rq];
        const float mp1 = Mx[(wid ^ 4) * 16 + 8 + rq];
        const float ms0 = fminf(m0, mp0), ms1 = fminf(m1, mp1);
        const float s0 = ex2(ms0 - m0), s1 = ex2(ms1 - m1);
        l0 *= s0;  l1 *= s1;
        #pragma unroll
        for (int j = 0; j < 8; j++) {
            O[j * 4 + 0] *= s0;  O[j * 4 + 1] *= s0;
            O[j * 4 + 2] *= s1;  O[j * 4 + 3] *= s1;
        }
    }
    const int rb = wrow * 16 + rq;
    const int cb = (lane & 3) * 2;
    if (half == 0) {
        #pragma unroll
        for (int j = 0; j < 8; j++) {
            Ob[rb * 66 + j * 8 + cb]           = O[j * 4 + 0];
            Ob[rb * 66 + j * 8 + cb + 1]       = O[j * 4 + 1];
            Ob[(rb + 8) * 66 + j * 8 + cb]     = O[j * 4 + 2];
            Ob[(rb + 8) * 66 + j * 8 + cb + 1] = O[j * 4 + 3];
        }
        if ((lane & 3) == 0) { Lb[rb] = l0; Lb[rb + 8] = l1; }
    }
    __syncthreads();
    if (half == 1) {
        l0 += Lb[rb];
        l1 += Lb[rb + 8];
        const float i0 = 0.1f / l0, i1 = 0.1f / l1;
        const int r0 = blockIdx.x * TM + rb;
        const int r1 = r0 + 8;
        #pragma unroll
        for (int j = 0; j < 8; j++) {
            const int col = j * 8 + cb;
            float2 pv0 = *(const float2*)(p + (size_t)r0 * D_DIM + col);
            float2 pv1 = *(const float2*)(p + (size_t)r1 * D_DIM + col);
            float2 o0, o1;
            o0.x = 0.9f * pv0.x + (O[j * 4 + 0] + Ob[rb * 66 + col])           * i0;
            o0.y = 0.9f * pv0.y + (O[j * 4 + 1] + Ob[rb * 66 + col + 1])       * i0;
            o1.x = 0.9f * pv1.x + (O[j * 4 + 2] + Ob[(rb + 8) * 66 + col])     * i1;
            o1.y = 0.9f * pv1.y + (O[j * 4 + 3] + Ob[(rb + 8) * 66 + col + 1]) * i1;
            *(float2*)(out + (size_t)r0 * D_DIM + col) = o0;
            *(float2*)(out + (size_t)r1 * D_DIM + col) = o1;
        }
    }
}

extern "C" void kernel_launch(void* const* d_in, const int* in_sizes, int n_in,
                              void* d_out, int out_size) {
    const float* p = (const float*)d_in[0];
    float* out = (float*)d_out;
    const int n = in_sizes[0];
    const int N = n / D_DIM;
    prep_kernel<<<(n + 255) / 256, 256>>>(p, n);
    attn_kernel<<<N / TM, NTH>>>(p, out, N);
}